// round 6
// baseline (speedup 1.0000x reference)
#include <cuda_runtime.h>
#include <cstdint>

// x [B=512, T=128, C=512] fp32; Wq/Wk/Wv [H=64, C=512]; out [B, T, 64] fp32.
// 512-thread CTA per batch (16 warps, 4/SMSP). mma.sync m16n8k8 tf32.
// cp.async double-buffered projection tiles; balanced causal work split.
#define TT 128
#define CC 512
#define HH 64
#define KT 32
#define NT_THREADS 512

// pitches (floats); pitch % 32 == 4 => conflict-free fragment LDS
#define PT 36     // X/W staging tiles [rows][32] raw fp32
#define PQ 68     // Qs/Ks [128][64] tf32
#define PVT 132   // Vt [64][128] tf32
#define PS 132    // S/P [128][128]

// smem float offsets
#define OFF_Q   0
#define OFF_K   (128 * PQ)                    // 8704
#define OFF_VT  (2 * 128 * PQ)                // 17408
#define OFF_SCR (OFF_VT + 64 * PVT)           // 25856
#define OFF_S   OFF_SCR
#define XBUF(bf) (OFF_SCR + (bf) * (128 * PT))
#define WBUF(bf) (OFF_SCR + 2 * 128 * PT + (bf) * (192 * PT))
#define SMEM_FLOATS (OFF_SCR + 2 * 128 * PT + 2 * 192 * PT)   // 48896 = 195584 B

__device__ __forceinline__ float tf32r(float f) {
    uint32_t u;
    asm("cvt.rna.tf32.f32 %0, %1;" : "=r"(u) : "f"(f));
    return __uint_as_float(u);
}
__device__ __forceinline__ uint32_t tf32b(float f) {
    uint32_t u;
    asm("cvt.rna.tf32.f32 %0, %1;" : "=r"(u) : "f"(f));
    return u;
}
__device__ __forceinline__ uint32_t fb(float f) { return __float_as_uint(f); }

__device__ __forceinline__ uint32_t smem_u32(const void* p) {
    uint32_t a;
    asm("{ .reg .u64 t; cvta.to.shared.u64 t, %1; cvt.u32.u64 %0, t; }" : "=r"(a) : "l"(p));
    return a;
}
__device__ __forceinline__ void cp16(uint32_t dst, const float* src) {
    asm volatile("cp.async.ca.shared.global [%0], [%1], 16;" :: "r"(dst), "l"(src));
}
#define CP_COMMIT() asm volatile("cp.async.commit_group;" ::: "memory")
#define CP_WAIT1()  asm volatile("cp.async.wait_group 1;"  ::: "memory")
#define CP_WAIT0()  asm volatile("cp.async.wait_group 0;"  ::: "memory")

__device__ __forceinline__ void mma8(float* d, const uint32_t* a, const uint32_t* b) {
    asm volatile(
        "mma.sync.aligned.m16n8k8.row.col.f32.tf32.tf32.f32 "
        "{%0,%1,%2,%3}, {%4,%5,%6,%7}, {%8,%9}, {%0,%1,%2,%3};"
        : "+f"(d[0]), "+f"(d[1]), "+f"(d[2]), "+f"(d[3])
        : "r"(a[0]), "r"(a[1]), "r"(a[2]), "r"(a[3]), "r"(b[0]), "r"(b[1]));
}

__global__ __launch_bounds__(NT_THREADS, 1)
void attn_hmma4_kernel(const float* __restrict__ x,
                       const float* __restrict__ Wq,
                       const float* __restrict__ Wk,
                       const float* __restrict__ Wv,
                       float* __restrict__ out)
{
    extern __shared__ float sm[];
    float* Qs = sm + OFF_Q;
    float* Ks = sm + OFF_K;
    float* Vt = sm + OFF_VT;
    float* Ss = sm + OFF_S;
    const uint32_t sb = smem_u32(sm);

    const int tid  = threadIdx.x;
    const int wid  = tid >> 5;
    const int lane = tid & 31;
    const int l4   = lane >> 2;
    const int lk   = lane & 3;
    const int b    = blockIdx.x;
    const float* xb = x + (size_t)b * TT * CC;

    const int wr = wid >> 2;        // 0..3 : row-pair group
    const int wc = wid & 3;         // 0..3 : column group
    // balanced causal row mapping: this warp owns row tiles {wr, 7-wr}
    const int rt0 = wr * 16;
    const int rt1 = (7 - wr) * 16;

    // --- cp.async tile stagers (512 threads) ---
    auto issue_chunk = [&](int ch, int bf) {
        const int k0 = ch * KT;
        const uint32_t xB = sb + XBUF(bf) * 4;
        const uint32_t wB = sb + WBUF(bf) * 4;
#pragma unroll
        for (int q = 0; q < 2; q++) {            // X tile [128][32] = 1024 float4
            int idx = q * NT_THREADS + tid;
            int row = idx >> 3, c4 = idx & 7;
            cp16(xB + (uint32_t)(row * PT + c4 * 4) * 4, xb + row * CC + k0 + c4 * 4);
        }
#pragma unroll
        for (int q = 0; q < 3; q++) {            // W tile [192][32] = 1536 float4
            int idx = q * NT_THREADS + tid;
            int row = idx >> 3, c4 = idx & 7;
            const float* Wp = (row < 64) ? (Wq + row * CC)
                            : (row < 128) ? (Wk + (row - 64) * CC)
                                          : (Wv + (row - 128) * CC);
            cp16(wB + (uint32_t)(row * PT + c4 * 4) * 4, Wp + k0 + c4 * 4);
        }
        CP_COMMIT();
    };

    // ============ Phase 1: [Q|K|V] = x @ W^T (16 chunks, double-buffered) ============
    float acc[2][6][4];
#pragma unroll
    for (int i = 0; i < 2; i++)
#pragma unroll
        for (int j = 0; j < 6; j++)
#pragma unroll
            for (int k = 0; k < 4; k++) acc[i][j][k] = 0.0f;

    const int nb1 = wc * 48;   // 6 n-tiles of 8 cols

    issue_chunk(0, 0);
    issue_chunk(1, 1);

#pragma unroll 1
    for (int ch = 0; ch < 16; ch++) {
        if (ch == 15) { CP_WAIT0(); } else { CP_WAIT1(); }
        __syncthreads();
        const int bf = ch & 1;
        const float* Xs  = sm + XBUF(bf);
        const float* Wsm = sm + WBUF(bf);

#pragma unroll
        for (int ks = 0; ks < 4; ks++) {
            const int kk = ks * 8;
            uint32_t a[2][4];
#pragma unroll
            for (int mt = 0; mt < 2; mt++) {
                const int rb = mt ? rt1 : rt0;
                const float* ap = Xs + (rb + l4) * PT + kk + lk;
                a[mt][0] = tf32b(ap[0]);
                a[mt][1] = tf32b(ap[8 * PT]);
                a[mt][2] = tf32b(ap[4]);
                a[mt][3] = tf32b(ap[8 * PT + 4]);
            }
#pragma unroll
            for (int nt = 0; nt < 6; nt++) {
                const float* bp = Wsm + (nb1 + nt * 8 + l4) * PT + kk + lk;
                uint32_t b2[2] = { tf32b(bp[0]), tf32b(bp[4]) };
                mma8(acc[0][nt], a[0], b2);
                mma8(acc[1][nt], a[1], b2);
            }
        }
        __syncthreads();
        if (ch < 14) issue_chunk(ch + 2, ch & 1);
    }

    // Epilogue: route D frags to Qs / Ks / Vt (tf32-rounded)
#pragma unroll
    for (int mt = 0; mt < 2; mt++) {
        const int r0 = (mt ? rt1 : rt0) + l4;
#pragma unroll
        for (int nt = 0; nt < 6; nt++) {
            const int c0 = nb1 + nt * 8 + 2 * lk;
            float d0 = tf32r(acc[mt][nt][0]), d1 = tf32r(acc[mt][nt][1]);
            float d2 = tf32r(acc[mt][nt][2]), d3 = tf32r(acc[mt][nt][3]);
            if (c0 < 64) {
                *reinterpret_cast<float2*>(Qs + r0 * PQ + c0)       = make_float2(d0, d1);
                *reinterpret_cast<float2*>(Qs + (r0 + 8) * PQ + c0) = make_float2(d2, d3);
            } else if (c0 < 128) {
                *reinterpret_cast<float2*>(Ks + r0 * PQ + (c0 - 64))       = make_float2(d0, d1);
                *reinterpret_cast<float2*>(Ks + (r0 + 8) * PQ + (c0 - 64)) = make_float2(d2, d3);
            } else {
                const int h = c0 - 128;
                Vt[h * PVT + r0]           = d0;
                Vt[(h + 1) * PVT + r0]     = d1;
                Vt[h * PVT + r0 + 8]       = d2;
                Vt[(h + 1) * PVT + r0 + 8] = d3;
            }
        }
    }
    __syncthreads();

    // ============ Phase 2: S = Q K^T — balanced causal tiles ============
    // warp handles col tiles nt = wc, wc+4, wc+8, wc+12 (u=0..3); tile allowed if nt <= 2i+1
    {
        const int ntmax0 = 2 * wr + 1;            // for rt0
        const int ntmax1 = 15 - 2 * wr;           // for rt1
        float accS0[4][4], accS1[4][4];
#pragma unroll
        for (int j = 0; j < 4; j++)
#pragma unroll
            for (int k = 0; k < 4; k++) { accS0[j][k] = 0.0f; accS1[j][k] = 0.0f; }

#pragma unroll
        for (int ks = 0; ks < 8; ks++) {
            const int kk = ks * 8;
            uint32_t a0[4], a1[4];
            {
                const float* ap = Qs + (rt0 + l4) * PQ + kk + lk;
                a0[0] = fb(ap[0]); a0[1] = fb(ap[8 * PQ]);
                a0[2] = fb(ap[4]); a0[3] = fb(ap[8 * PQ + 4]);
            }
            {
                const float* ap = Qs + (rt1 + l4) * PQ + kk + lk;
                a1[0] = fb(ap[0]); a1[1] = fb(ap[8 * PQ]);
                a1[2] = fb(ap[4]); a1[3] = fb(ap[8 * PQ + 4]);
            }
#pragma unroll
            for (int u = 0; u < 4; u++) {
                const int nt = wc + 4 * u;
                if (nt <= ntmax1) {
                    const float* bp = Ks + (nt * 8 + l4) * PQ + kk + lk;
                    uint32_t b2[2] = { fb(bp[0]), fb(bp[4]) };
                    mma8(accS1[u], a1, b2);
                    if (nt <= ntmax0) mma8(accS0[u], a0, b2);
                }
            }
        }
#pragma unroll
        for (int u = 0; u < 4; u++) {
            const int nt = wc + 4 * u;
            const int c0 = nt * 8 + 2 * lk;
            if (nt <= ntmax1) {
                const int r0 = rt1 + l4;
                *reinterpret_cast<float2*>(Ss + r0 * PS + c0) =
                    make_float2(accS1[u][0], accS1[u][1]);
                *reinterpret_cast<float2*>(Ss + (r0 + 8) * PS + c0) =
                    make_float2(accS1[u][2], accS1[u][3]);
            }
            if (nt <= ntmax0) {
                const int r0 = rt0 + l4;
                *reinterpret_cast<float2*>(Ss + r0 * PS + c0) =
                    make_float2(accS0[u][0], accS0[u][1]);
                *reinterpret_cast<float2*>(Ss + (r0 + 8) * PS + c0) =
                    make_float2(accS0[u][2], accS0[u][3]);
            }
        }
    }
    __syncthreads();

    // ============ Softmax (scale + causal mask), P stored tf32, normalized ============
    {
        for (int rr = 0; rr < 8; rr++) {
            const int r = wid * 8 + rr;
            float v0 = Ss[r * PS + lane];
            float v1 = Ss[r * PS + lane + 32];
            float v2 = Ss[r * PS + lane + 64];
            float v3 = Ss[r * PS + lane + 96];
            v0 = (lane      <= r) ? v0 * 0.125f : -1e30f;
            v1 = (lane + 32 <= r) ? v1 * 0.125f : -1e30f;
            v2 = (lane + 64 <= r) ? v2 * 0.125f : -1e30f;
            v3 = (lane + 96 <= r) ? v3 * 0.125f : -1e30f;
            float m = fmaxf(fmaxf(v0, v1), fmaxf(v2, v3));
#pragma unroll
            for (int o = 16; o > 0; o >>= 1)
                m = fmaxf(m, __shfl_xor_sync(0xffffffffu, m, o));
            float e0 = __expf(v0 - m), e1 = __expf(v1 - m);
            float e2 = __expf(v2 - m), e3 = __expf(v3 - m);
            float s = e0 + e1 + e2 + e3;
#pragma unroll
            for (int o = 16; o > 0; o >>= 1)
                s += __shfl_xor_sync(0xffffffffu, s, o);
            const float inv = 1.0f / s;
            Ss[r * PS + lane]      = tf32r(e0 * inv);
            Ss[r * PS + lane + 32] = tf32r(e1 * inv);
            Ss[r * PS + lane + 64] = tf32r(e2 * inv);
            Ss[r * PS + lane + 96] = tf32r(e3 * inv);
        }
    }
    __syncthreads();

    // ============ Phase 3: O = P @ V — skip all-zero P k-tiles ============
    {
        const int nb3 = wc * 16;                  // 2 n-tiles of 8 cols
        const int ksmax0 = 2 * wr + 1;            // rows rt0: P zero beyond
        const int ksmax1 = 15 - 2 * wr;           // rows rt1
        float accO[2][2][4];
#pragma unroll
        for (int i = 0; i < 2; i++)
#pragma unroll
            for (int j = 0; j < 2; j++)
#pragma unroll
                for (int k = 0; k < 4; k++) accO[i][j][k] = 0.0f;

#pragma unroll
        for (int ks = 0; ks < 16; ks++) {
            if (ks <= ksmax1) {
                const int kk = ks * 8;
                uint32_t b2[2][2];
#pragma unroll
                for (int nt = 0; nt < 2; nt++) {
                    const float* bp = Vt + (nb3 + nt * 8 + l4) * PVT + kk + lk;
                    b2[nt][0] = fb(bp[0]); b2[nt][1] = fb(bp[4]);
                }
                uint32_t a1[4];
                {
                    const float* ap = Ss + (rt1 + l4) * PS + kk + lk;
                    a1[0] = fb(ap[0]); a1[1] = fb(ap[8 * PS]);
                    a1[2] = fb(ap[4]); a1[3] = fb(ap[8 * PS + 4]);
                }
                mma8(accO[1][0], a1, b2[0]);
                mma8(accO[1][1], a1, b2[1]);
                if (ks <= ksmax0) {
                    uint32_t a0[4];
                    const float* ap = Ss + (rt0 + l4) * PS + kk + lk;
                    a0[0] = fb(ap[0]); a0[1] = fb(ap[8 * PS]);
                    a0[2] = fb(ap[4]); a0[3] = fb(ap[8 * PS + 4]);
                    mma8(accO[0][0], a0, b2[0]);
                    mma8(accO[0][1], a0, b2[1]);
                }
            }
        }

#pragma unroll
        for (int mt = 0; mt < 2; mt++) {
            const int r0 = (mt ? rt1 : rt0) + l4;
#pragma unroll
            for (int nt = 0; nt < 2; nt++) {
                const int c0 = nb3 + nt * 8 + 2 * lk;
                *reinterpret_cast<float2*>(out + ((size_t)b * TT + r0) * HH + c0) =
                    make_float2(accO[mt][nt][0], accO[mt][nt][1]);
                *reinterpret_cast<float2*>(out + ((size_t)b * TT + r0 + 8) * HH + c0) =
                    make_float2(accO[mt][nt][2], accO[mt][nt][3]);
            }
        }
    }
}

extern "C" void kernel_launch(void* const* d_in, const int* in_sizes, int n_in,
                              void* d_out, int out_size)
{
    const float* x  = (const float*)d_in[0];
    const float* Wq = (const float*)d_in[1];
    const float* Wk = (const float*)d_in[2];
    const float* Wv = (const float*)d_in[3];
    float* out = (float*)d_out;

    const int B = in_sizes[0] / (TT * CC);                         // 512
    const size_t smem_bytes = (size_t)SMEM_FLOATS * sizeof(float); // 195584

    cudaFuncSetAttribute(attn_hmma4_kernel,
                         cudaFuncAttributeMaxDynamicSharedMemorySize,
                         (int)smem_bytes);
    attn_hmma4_kernel<<<B, NT_THREADS, smem_bytes>>>(x, Wq, Wk, Wv, out);
}